// round 8
// baseline (speedup 1.0000x reference)
#include <cuda_runtime.h>
#include <cuda_bf16.h>

// out[i,j,:] = W[d_res] + W[66+d_token] + same_entity*W[132] + W[133+d_chain]
//
// d_res   = same_chain ? clip(res_i-res_j+32, 0, 64) : 65
// d_token = same_chain && res_i==res_j ? clip(tok_i-tok_j+32, 0, 64) : 65
// d_chain = !same_chain ? clip(sym_i-sym_j+2, 0, 4) : 5
//
// Pure streaming-store kernel: 536 MB fp32 out, HBM-write bound.
// Persistent CTAs (1024 thr, 2/SM -> 100% occ) so the 91KB smem W-table
// is amortized over ~3.5 i-rows per CTA and store MLP is 4x round 0.

#define NTHREADS 1024
#define NWARPS   32
#define WROWS    139
#define WCOLS4   32      // 128 floats = 32 float4

__global__ __launch_bounds__(NTHREADS, 2)
void relpos_kernel(const float* __restrict__ feats,
                   const float* __restrict__ W,
                   float* __restrict__ out, int n) {
    extern __shared__ float smem[];
    float4* Wsh   = (float4*)smem;                       // [139][32] float4
    int*    s_res = (int*)(smem + WROWS * 128);
    int*    s_tok = s_res  + n;
    int*    s_asy = s_tok  + n;
    int*    s_ent = s_asy  + n;
    int*    s_sym = s_ent  + n;

    const int tid = threadIdx.x;

    // Load W into shared
    const float4* W4 = (const float4*)W;
    #pragma unroll 5
    for (int idx = tid; idx < WROWS * WCOLS4; idx += NTHREADS)
        Wsh[idx] = W4[idx];

    // Load integer index features into shared
    if (tid < n) {
        const float* fj = feats + (size_t)tid * 10;
        s_res[tid] = (int)fj[0];
        s_tok[tid] = (int)fj[1];
        s_asy[tid] = (int)fj[2];
        s_ent[tid] = (int)fj[3];
        s_sym[tid] = (int)fj[4];
    }
    __syncthreads();

    const int lane = tid & 31;
    const int wid  = tid >> 5;

    // Register-resident constant rows (per-lane float4 column slice), i-invariant
    const float4 w132 = Wsh[132 * WCOLS4 + lane];             // entity row
    const float4 wb0  = Wsh[65  * WCOLS4 + lane];             // d_res = 65
    const float4 wb1  = Wsh[131 * WCOLS4 + lane];             // d_token = 65 (66+65)
    float4 wbase;                                              // off-chain base
    wbase.x = wb0.x + wb1.x; wbase.y = wb0.y + wb1.y;
    wbase.z = wb0.z + wb1.z; wbase.w = wb0.w + wb1.w;
    const float4 wch5 = Wsh[138 * WCOLS4 + lane];             // d_chain = 5 (133+5)

    // Persistent loop over i-rows
    for (int i = blockIdx.x; i < n; i += gridDim.x) {
        const int res_i = s_res[i];
        const int tok_i = s_tok[i];
        const int asy_i = s_asy[i];
        const int ent_i = s_ent[i];
        const int sym_i = s_sym[i];

        float4* outp = (float4*)out + (size_t)i * n * WCOLS4 + lane;

        for (int j = wid; j < n; j += NWARPS) {
            const int  dres = res_i - s_res[j];
            const bool same = (asy_i == s_asy[j]);             // warp-uniform
            const float ment = (ent_i == s_ent[j]) ? 1.0f : 0.0f;

            float4 acc;
            if (same) {
                int d_res = min(max(dres + 32, 0), 64);
                int d_tok = 65;
                if (dres == 0)
                    d_tok = min(max(tok_i - s_tok[j] + 32, 0), 64);
                float4 a = Wsh[d_res * WCOLS4 + lane];
                float4 b = Wsh[(66 + d_tok) * WCOLS4 + lane];
                acc.x = a.x + b.x + wch5.x;
                acc.y = a.y + b.y + wch5.y;
                acc.z = a.z + b.z + wch5.z;
                acc.w = a.w + b.w + wch5.w;
            } else {
                int d_ch = min(max(sym_i - s_sym[j] + 2, 0), 4);
                float4 c = Wsh[(133 + d_ch) * WCOLS4 + lane];
                acc.x = wbase.x + c.x;
                acc.y = wbase.y + c.y;
                acc.z = wbase.z + c.z;
                acc.w = wbase.w + c.w;
            }
            acc.x = fmaf(ment, w132.x, acc.x);
            acc.y = fmaf(ment, w132.y, acc.y);
            acc.z = fmaf(ment, w132.z, acc.z);
            acc.w = fmaf(ment, w132.w, acc.w);

            __stcs(&outp[(size_t)j * WCOLS4], acc);            // streaming store
        }
    }
}

extern "C" void kernel_launch(void* const* d_in, const int* in_sizes, int n_in,
                              void* d_out, int out_size) {
    const float* feats = (const float*)d_in[0];
    const float* W     = (const float*)d_in[1];
    float*       out   = (float*)d_out;

    const int n = in_sizes[0] / 10;   // 1024
    const size_t smem = (size_t)WROWS * 128 * sizeof(float) + (size_t)5 * n * sizeof(int);

    cudaFuncSetAttribute(relpos_kernel,
                         cudaFuncAttributeMaxDynamicSharedMemorySize, (int)smem);

    int dev = 0, nsm = 148;
    cudaGetDevice(&dev);
    cudaDeviceGetAttribute(&nsm, cudaDevAttrMultiProcessorCount, dev);

    relpos_kernel<<<2 * nsm, NTHREADS, smem>>>(feats, W, out, n);
}

// round 9
// speedup vs baseline: 1.1816x; 1.1816x over previous
#include <cuda_runtime.h>
#include <cuda_bf16.h>

// out[i,j,:] = W[d_res] + W[66+d_token] + same_entity*W[132] + W[133+d_chain]
//
// d_res   = same_chain ? clip(res_i-res_j+32, 0, 64) : 65
// d_token = same_chain && res_i==res_j ? clip(tok_i-tok_j+32, 0, 64) : 65
// d_chain = !same_chain ? clip(sym_i-sym_j+2, 0, 4) : 5
//
// ~98% of pairs are off-chain: those need ZERO smem reads — the 5 possible
// off-chain row-sums live in registers, selected by a warp-uniform branch.
// L1/LSU then carries (almost) only the irreducible 536MB store stream.

#define NTHREADS 512
#define NWARPS   16
#define WROWS    139
#define WCOLS4   32      // 128 floats = 32 float4

__device__ __forceinline__ float4 f4add(float4 a, float4 b) {
    return make_float4(a.x + b.x, a.y + b.y, a.z + b.z, a.w + b.w);
}

__global__ __launch_bounds__(NTHREADS)
void relpos_kernel(const float* __restrict__ feats,
                   const float* __restrict__ W,
                   float* __restrict__ out, int n) {
    extern __shared__ float smem[];
    float4* Wsh   = (float4*)smem;                       // [139][32] float4
    int*    s_res = (int*)(smem + WROWS * 128);
    int*    s_tok = s_res  + n;
    int*    s_asy = s_tok  + n;
    int*    s_ent = s_asy  + n;
    int*    s_sym = s_ent  + n;

    const int tid = threadIdx.x;

    // Load W into shared
    const float4* W4 = (const float4*)W;
    #pragma unroll 5
    for (int idx = tid; idx < WROWS * WCOLS4; idx += NTHREADS)
        Wsh[idx] = W4[idx];

    // Load integer index features into shared
    for (int j = tid; j < n; j += NTHREADS) {
        const float* fj = feats + (size_t)j * 10;
        s_res[j] = (int)fj[0];
        s_tok[j] = (int)fj[1];
        s_asy[j] = (int)fj[2];
        s_ent[j] = (int)fj[3];
        s_sym[j] = (int)fj[4];
    }
    __syncthreads();

    const int lane = tid & 31;
    const int wid  = tid >> 5;

    // i-invariant register rows (per-lane float4 column slice)
    const float4 w132 = Wsh[132 * WCOLS4 + lane];             // entity row
    const float4 wch5 = Wsh[138 * WCOLS4 + lane];             // on-chain chain bin
    const float4 wbase = f4add(Wsh[65  * WCOLS4 + lane],      // d_res=65
                               Wsh[131 * WCOLS4 + lane]);     // d_token=65
    // All 5 possible off-chain totals, fully register-resident:
    const float4 woff0 = f4add(wbase, Wsh[133 * WCOLS4 + lane]);
    const float4 woff1 = f4add(wbase, Wsh[134 * WCOLS4 + lane]);
    const float4 woff2 = f4add(wbase, Wsh[135 * WCOLS4 + lane]);
    const float4 woff3 = f4add(wbase, Wsh[136 * WCOLS4 + lane]);
    const float4 woff4 = f4add(wbase, Wsh[137 * WCOLS4 + lane]);

    // Persistent loop over i-rows
    for (int i = blockIdx.x; i < n; i += gridDim.x) {
        const int res_i = s_res[i];
        const int tok_i = s_tok[i];
        const int asy_i = s_asy[i];
        const int ent_i = s_ent[i];
        const int sym_i = s_sym[i];

        float4* outp = (float4*)out + (size_t)i * n * WCOLS4 + lane;

        for (int j = wid; j < n; j += NWARPS) {
            const bool same = (asy_i == s_asy[j]);             // warp-uniform
            const float ment = (ent_i == s_ent[j]) ? 1.0f : 0.0f;

            float4 acc;
            if (same) {                                        // ~1.6% of pairs
                const int dres = res_i - s_res[j];
                int d_res = min(max(dres + 32, 0), 64);
                int d_tok = 65;
                if (dres == 0)
                    d_tok = min(max(tok_i - s_tok[j] + 32, 0), 64);
                float4 a = Wsh[d_res * WCOLS4 + lane];
                float4 b = Wsh[(66 + d_tok) * WCOLS4 + lane];
                acc = f4add(f4add(a, b), wch5);
            } else {                                           // ~98.4%: no LDS
                const int d_ch = min(max(sym_i - s_sym[j] + 2, 0), 4);
                // warp-uniform select among register-resident rows
                if      (d_ch == 0) acc = woff0;
                else if (d_ch == 1) acc = woff1;
                else if (d_ch == 2) acc = woff2;
                else if (d_ch == 3) acc = woff3;
                else                acc = woff4;
            }
            acc.x = fmaf(ment, w132.x, acc.x);
            acc.y = fmaf(ment, w132.y, acc.y);
            acc.z = fmaf(ment, w132.z, acc.z);
            acc.w = fmaf(ment, w132.w, acc.w);

            outp[(size_t)j * WCOLS4] = acc;
        }
    }
}

extern "C" void kernel_launch(void* const* d_in, const int* in_sizes, int n_in,
                              void* d_out, int out_size) {
    const float* feats = (const float*)d_in[0];
    const float* W     = (const float*)d_in[1];
    float*       out   = (float*)d_out;

    const int n = in_sizes[0] / 10;   // 1024
    const size_t smem = (size_t)WROWS * 128 * sizeof(float) + (size_t)5 * n * sizeof(int);

    cudaFuncSetAttribute(relpos_kernel,
                         cudaFuncAttributeMaxDynamicSharedMemorySize, (int)smem);

    int dev = 0, nsm = 148;
    cudaGetDevice(&dev);
    cudaDeviceGetAttribute(&nsm, cudaDevAttrMultiProcessorCount, dev);

    relpos_kernel<<<2 * nsm, NTHREADS, smem>>>(feats, W, out, n);
}